// round 1
// baseline (speedup 1.0000x reference)
#include <cuda_runtime.h>
#include <math.h>

#define BB 2
#define NN 1024
#define DD 512
#define HH 8
#define DHH 64
#define HD 512
#define FFD 2048
#define DEPTH 4

// ---------------- device scratch (no allocation allowed) ----------------
__device__ float g_x  [BB*NN*DD];
__device__ float g_xn [BB*NN*DD];
__device__ float g_qkv[BB*NN*3*HD];
__device__ float g_ws [BB*NN*HD];
__device__ float g_AC [(size_t)BB*HH*NN*NN];
__device__ float g_BD [(size_t)BB*HH*NN*NN];
__device__ float g_attn[(size_t)BB*HH*NN*NN];
__device__ float g_av [BB*NN*HD];
__device__ float g_h1 [BB*NN*FFD];

// ---------------- simple copies ----------------
__global__ void copy_in_kernel(const float* __restrict__ src) {
    int i = blockIdx.x * 256 + threadIdx.x;
    g_x[i] = src[i];
}
__global__ void copy_out_kernel(float* __restrict__ dst) {
    int i = blockIdx.x * 256 + threadIdx.x;
    dst[i] = g_x[i];
}

// ---------------- layernorm: one block (128 thr) per row of 512 ----------------
__global__ void ln_kernel(const float* __restrict__ x, const float* __restrict__ g,
                          const float* __restrict__ bta, float* __restrict__ y) {
    __shared__ float red[128];
    int row = blockIdx.x;
    int tid = threadIdx.x;
    const float4* xr = (const float4*)(x + (size_t)row * DD);
    float4 v = xr[tid];
    red[tid] = v.x + v.y + v.z + v.w;
    __syncthreads();
    for (int o = 64; o > 0; o >>= 1) { if (tid < o) red[tid] += red[tid + o]; __syncthreads(); }
    float mean = red[0] * (1.0f / DD);
    __syncthreads();
    float dx = v.x - mean, dy = v.y - mean, dz = v.z - mean, dw = v.w - mean;
    red[tid] = dx*dx + dy*dy + dz*dz + dw*dw;
    __syncthreads();
    for (int o = 64; o > 0; o >>= 1) { if (tid < o) red[tid] += red[tid + o]; __syncthreads(); }
    float rstd = rsqrtf(red[0] * (1.0f / DD) + 1e-5f);
    float4 gv = ((const float4*)g)[tid];
    float4 bv = ((const float4*)bta)[tid];
    float4 o4;
    o4.x = dx * rstd * gv.x + bv.x;
    o4.y = dy * rstd * gv.y + bv.y;
    o4.z = dz * rstd * gv.z + bv.z;
    o4.w = dw * rstd * gv.w + bv.w;
    ((float4*)(y + (size_t)row * DD))[tid] = o4;
}

// ---------------- generic 128x128x8 SGEMM, 8x8 microtile, 256 threads ----------------
__device__ __forceinline__ float gelu_exact(float v) {
    return 0.5f * v * (1.0f + erff(v * 0.70710678118654752f));
}

template<bool ACCUM, bool BIAS, bool RES, bool GELU_>
__global__ void sgemm128(const float* __restrict__ A, const float* __restrict__ Bm,
                         float* __restrict__ C, int M, int Nc, int K,
                         const float* __restrict__ bias, const float* __restrict__ res) {
    __shared__ float As[8][128];
    __shared__ float Bs[8][128];
    const int tid = threadIdx.x;
    const int tx = tid & 15, ty = tid >> 4;
    const int row0 = blockIdx.y * 128;
    const int col0 = blockIdx.x * 128;
    float acc[8][8];
#pragma unroll
    for (int r = 0; r < 8; r++)
#pragma unroll
        for (int c = 0; c < 8; c++) acc[r][c] = 0.f;

    const int ar  = tid >> 1;          // A tile row 0..127
    const int ak0 = (tid & 1) * 4;     // A k sub-offset
    const int br  = tid >> 5;          // B tile k-row 0..7
    const int bc  = (tid & 31) * 4;    // B col offset

    for (int k0 = 0; k0 < K; k0 += 8) {
        float4 av = *(const float4*)(A + (size_t)(row0 + ar) * K + k0 + ak0);
        As[ak0 + 0][ar] = av.x; As[ak0 + 1][ar] = av.y;
        As[ak0 + 2][ar] = av.z; As[ak0 + 3][ar] = av.w;
        float4 bv = *(const float4*)(Bm + (size_t)(k0 + br) * Nc + col0 + bc);
        *(float4*)&Bs[br][bc] = bv;
        __syncthreads();
#pragma unroll
        for (int kk = 0; kk < 8; kk++) {
            float a[8], b[8];
#pragma unroll
            for (int r = 0; r < 8; r++) a[r] = As[kk][ty * 8 + r];
#pragma unroll
            for (int c = 0; c < 8; c++) b[c] = Bs[kk][tx * 8 + c];
#pragma unroll
            for (int r = 0; r < 8; r++)
#pragma unroll
                for (int c = 0; c < 8; c++) acc[r][c] = fmaf(a[r], b[c], acc[r][c]);
        }
        __syncthreads();
    }
#pragma unroll
    for (int r = 0; r < 8; r++) {
        int row = row0 + ty * 8 + r;
#pragma unroll
        for (int c = 0; c < 8; c++) {
            int col = col0 + tx * 8 + c;
            size_t idx = (size_t)row * Nc + col;
            float v = acc[r][c];
            if (ACCUM) v += C[idx];
            if (BIAS)  v += bias[col];
            if (RES)   v += res[idx];
            if (GELU_) v = gelu_exact(v);
            C[idx] = v;
        }
    }
}

// ---------------- batched scores: AC = q.k^T, BD = q.ws^T  (per b,h; K=64) ----------------
// output layout (b,h,i,j) contiguous in j
__global__ void scores_kernel(const float* __restrict__ qkv, const float* __restrict__ ws,
                              const float* __restrict__ bias_pf,
                              float* __restrict__ AC, float* __restrict__ BD) {
    __shared__ float Qs[DHH][64];
    __shared__ float Ks[DHH][64];
    __shared__ float Ws[DHH][64];
    const int bh = blockIdx.z;
    const int b = bh >> 3, h = bh & 7;
    const int i0 = blockIdx.y << 6, j0 = blockIdx.x << 6;
    const int tid = threadIdx.x;
    const int tx = tid & 15, ty = tid >> 4;

    const int lrow = tid >> 2;
    const int ld0  = (tid & 3) << 4;
    const float* qbase = qkv + (size_t)(b * NN + i0 + lrow) * (3 * HD) + h * DHH;
    const float* kbase = qkv + (size_t)(b * NN + j0 + lrow) * (3 * HD) + HD + h * DHH;
    const float* wbase = ws  + (size_t)(b * NN + j0 + lrow) * HD + h * DHH;
    const float* pfb   = bias_pf + h * DHH;
#pragma unroll
    for (int t = 0; t < 4; t++) {
        int d = ld0 + t * 4;
        float4 qv = *(const float4*)(qbase + d);
        float4 pf = *(const float4*)(pfb + d);
        Qs[d + 0][lrow] = qv.x + pf.x; Qs[d + 1][lrow] = qv.y + pf.y;
        Qs[d + 2][lrow] = qv.z + pf.z; Qs[d + 3][lrow] = qv.w + pf.w;
        float4 kv = *(const float4*)(kbase + d);
        Ks[d + 0][lrow] = kv.x; Ks[d + 1][lrow] = kv.y;
        Ks[d + 2][lrow] = kv.z; Ks[d + 3][lrow] = kv.w;
        float4 wv = *(const float4*)(wbase + d);
        Ws[d + 0][lrow] = wv.x; Ws[d + 1][lrow] = wv.y;
        Ws[d + 2][lrow] = wv.z; Ws[d + 3][lrow] = wv.w;
    }
    __syncthreads();

    float ac[4][4], bd[4][4];
#pragma unroll
    for (int r = 0; r < 4; r++)
#pragma unroll
        for (int c = 0; c < 4; c++) { ac[r][c] = 0.f; bd[r][c] = 0.f; }

#pragma unroll 8
    for (int d = 0; d < DHH; d++) {
        float qa[4], kb[4], wb[4];
#pragma unroll
        for (int r = 0; r < 4; r++) qa[r] = Qs[d][(ty << 2) + r];
#pragma unroll
        for (int c = 0; c < 4; c++) { kb[c] = Ks[d][(tx << 2) + c]; wb[c] = Ws[d][(tx << 2) + c]; }
#pragma unroll
        for (int r = 0; r < 4; r++)
#pragma unroll
            for (int c = 0; c < 4; c++) {
                ac[r][c] = fmaf(qa[r], kb[c], ac[r][c]);
                bd[r][c] = fmaf(qa[r], wb[c], bd[r][c]);
            }
    }
    const size_t base = ((size_t)bh << 20);
#pragma unroll
    for (int r = 0; r < 4; r++) {
        int i = i0 + (ty << 2) + r;
        size_t rb = base + ((size_t)i << 10) + j0 + (tx << 2);
        float4 a4 = make_float4(ac[r][0], ac[r][1], ac[r][2], ac[r][3]);
        float4 b4 = make_float4(bd[r][0], bd[r][1], bd[r][2], bd[r][3]);
        *(float4*)(AC + rb) = a4;
        *(float4*)(BD + rb) = b4;
    }
}

// ---------------- dots = (AC + rel_shift(BD)/3)*SCALE, softmax over h, write attn ----------------
__global__ void softmax_kernel(const float* __restrict__ AC, const float* __restrict__ BD,
                               float* __restrict__ attn) {
    int idx = blockIdx.x * 256 + threadIdx.x;           // over b*N*N = 2M
    int b = idx >> 20;
    int ij = idx & ((1 << 20) - 1);
    int i = ij >> 10, j = ij & 1023;
    int m  = (i + 1) * NN + j;
    int i2 = m / (NN + 1);
    int k  = m - i2 * (NN + 1);
    size_t pb = ((size_t)(b * HH)) << 20;
    size_t shifted = ((size_t)i2 << 10) + (k - 1);
    float vals[8];
#pragma unroll
    for (int h = 0; h < 8; h++) {
        float ac = AC[pb + ((size_t)h << 20) + ij];
        float bd = (k != 0) ? BD[pb + ((size_t)h << 20) + shifted] : 0.f;
        vals[h] = (ac + bd * (1.0f / 3.0f)) * 0.125f;
    }
    float mx = vals[0];
#pragma unroll
    for (int h = 1; h < 8; h++) mx = fmaxf(mx, vals[h]);
    float s = 0.f;
#pragma unroll
    for (int h = 0; h < 8; h++) { vals[h] = expf(vals[h] - mx); s += vals[h]; }
    float inv = 1.0f / s;
#pragma unroll
    for (int h = 0; h < 8; h++) attn[pb + ((size_t)h << 20) + ij] = vals[h] * inv;
}

// ---------------- out[i,d] = sum_j attn[i,j] * v[j,d]  (per b,h) ----------------
__global__ void attnv_kernel(const float* __restrict__ attn, const float* __restrict__ qkv,
                             float* __restrict__ av) {
    __shared__ float As[64][64];   // [j][i]
    __shared__ float Vs[64][64];   // [j][d]
    const int bh = blockIdx.y;
    const int b = bh >> 3, h = bh & 7;
    const int i0 = blockIdx.x << 6;
    const int tid = threadIdx.x;
    const int tx = tid & 15, ty = tid >> 4;
    const int lrow = tid >> 2;
    const int ld0  = (tid & 3) << 4;

    float acc[4][4];
#pragma unroll
    for (int r = 0; r < 4; r++)
#pragma unroll
        for (int c = 0; c < 4; c++) acc[r][c] = 0.f;

    for (int j0 = 0; j0 < NN; j0 += 64) {
        const float* arow = attn + (((size_t)bh) << 20) + ((size_t)(i0 + lrow) << 10) + j0;
        const float* vrow = qkv + (size_t)(b * NN + j0 + lrow) * (3 * HD) + 2 * HD + h * DHH;
#pragma unroll
        for (int t = 0; t < 4; t++) {
            int o = ld0 + t * 4;
            float4 a4 = *(const float4*)(arow + o);
            As[o + 0][lrow] = a4.x; As[o + 1][lrow] = a4.y;
            As[o + 2][lrow] = a4.z; As[o + 3][lrow] = a4.w;
            float4 v4 = *(const float4*)(vrow + o);
            *(float4*)&Vs[lrow][o] = v4;
        }
        __syncthreads();
#pragma unroll 8
        for (int jj = 0; jj < 64; jj++) {
            float a[4], v[4];
#pragma unroll
            for (int r = 0; r < 4; r++) a[r] = As[jj][(ty << 2) + r];
#pragma unroll
            for (int c = 0; c < 4; c++) v[c] = Vs[jj][(tx << 2) + c];
#pragma unroll
            for (int r = 0; r < 4; r++)
#pragma unroll
                for (int c = 0; c < 4; c++) acc[r][c] = fmaf(a[r], v[c], acc[r][c]);
        }
        __syncthreads();
    }
#pragma unroll
    for (int r = 0; r < 4; r++) {
        int i = i0 + (ty << 2) + r;
        float4 o4 = make_float4(acc[r][0], acc[r][1], acc[r][2], acc[r][3]);
        *(float4*)(av + (size_t)(b * NN + i) * HD + h * DHH + (tx << 2)) = o4;
    }
}

// ---------------- host orchestration ----------------
extern "C" void kernel_launch(void* const* d_in, const int* in_sizes, int n_in,
                              void* d_out, int out_size) {
    (void)in_sizes; (void)n_in; (void)out_size;
    const float* in_x   = (const float*)d_in[0];
    const float* r_t    = (const float*)d_in[1];
    const float* r_c    = (const float*)d_in[2];
    const float* r_p    = (const float*)d_in[3];
    const float* bias_pf= (const float*)d_in[4];
    const float* ln1_g  = (const float*)d_in[5];
    const float* ln1_b  = (const float*)d_in[6];
    const float* w_qkv  = (const float*)d_in[7];
    const float* w_out  = (const float*)d_in[8];
    const float* b_out  = (const float*)d_in[9];
    const float* w_kt   = (const float*)d_in[10];
    const float* w_kc   = (const float*)d_in[11];
    const float* w_kp   = (const float*)d_in[12];
    const float* ln2_g  = (const float*)d_in[13];
    const float* ln2_b  = (const float*)d_in[14];
    const float* w_ff1  = (const float*)d_in[15];
    const float* b_ff1  = (const float*)d_in[16];
    const float* w_ff2  = (const float*)d_in[17];
    const float* b_ff2  = (const float*)d_in[18];

    float* out_x    = (float*)d_out;
    float* out_attn = out_x + (size_t)BB * NN * DD;

    float *p_x, *p_xn, *p_qkv, *p_ws, *p_AC, *p_BD, *p_attn, *p_av, *p_h1;
    cudaGetSymbolAddress((void**)&p_x,   g_x);
    cudaGetSymbolAddress((void**)&p_xn,  g_xn);
    cudaGetSymbolAddress((void**)&p_qkv, g_qkv);
    cudaGetSymbolAddress((void**)&p_ws,  g_ws);
    cudaGetSymbolAddress((void**)&p_AC,  g_AC);
    cudaGetSymbolAddress((void**)&p_BD,  g_BD);
    cudaGetSymbolAddress((void**)&p_attn,g_attn);
    cudaGetSymbolAddress((void**)&p_av,  g_av);
    cudaGetSymbolAddress((void**)&p_h1,  g_h1);

    const int M = BB * NN;   // 2048

    copy_in_kernel<<<(BB * NN * DD) / 256, 256>>>(in_x);

    for (int l = 0; l < DEPTH; l++) {
        // LN1
        ln_kernel<<<M, 128>>>(p_x, ln1_g + l * DD, ln1_b + l * DD, p_xn);
        // qkv = xn @ w_qkv[l]
        sgemm128<false,false,false,false><<<dim3(12, 16), 256>>>(
            p_xn, w_qkv + (size_t)l * DD * 3 * HD, p_qkv, M, 3 * HD, DD, nullptr, nullptr);
        // ws = r_t@w_kt + r_c@w_kc + r_p@w_kp  (rel_shift is linear -> fold BD terms)
        sgemm128<false,false,false,false><<<dim3(4, 16), 256>>>(
            r_t, w_kt + (size_t)l * DD * HD, p_ws, M, HD, DD, nullptr, nullptr);
        sgemm128<true,false,false,false><<<dim3(4, 16), 256>>>(
            r_c, w_kc + (size_t)l * DD * HD, p_ws, M, HD, DD, nullptr, nullptr);
        sgemm128<true,false,false,false><<<dim3(4, 16), 256>>>(
            r_p, w_kp + (size_t)l * DD * HD, p_ws, M, HD, DD, nullptr, nullptr);
        // AC / BD batched scores
        scores_kernel<<<dim3(16, 16, BB * HH), 256>>>(p_qkv, p_ws, bias_pf, p_AC, p_BD);
        // dots + rel_shift gather + softmax over heads
        float* attn_dst = (l == DEPTH - 1) ? out_attn : p_attn;
        softmax_kernel<<<(BB * NN * NN) / 256, 256>>>(p_AC, p_BD, attn_dst);
        // attn @ v
        attnv_kernel<<<dim3(16, BB * HH), 256>>>(attn_dst, p_qkv, p_av);
        // out projection + bias + residual (in place on x)
        sgemm128<false,true,true,false><<<dim3(4, 16), 256>>>(
            p_av, w_out + (size_t)l * HD * DD, p_x, M, DD, HD, b_out + l * DD, p_x);
        // LN2
        ln_kernel<<<M, 128>>>(p_x, ln2_g + l * DD, ln2_b + l * DD, p_xn);
        // FF1 + bias + exact GELU
        sgemm128<false,true,false,true><<<dim3(16, 16), 256>>>(
            p_xn, w_ff1 + (size_t)l * DD * FFD, p_h1, M, FFD, DD, b_ff1 + l * FFD, nullptr);
        // FF2 + bias + residual (in place on x)
        sgemm128<false,true,true,false><<<dim3(4, 16), 256>>>(
            p_h1, w_ff2 + (size_t)l * FFD * DD, p_x, M, DD, FFD, b_ff2 + l * DD, p_x);
    }

    copy_out_kernel<<<(BB * NN * DD) / 256, 256>>>(out_x);
}

// round 3
// speedup vs baseline: 2.1379x; 2.1379x over previous
#include <cuda_runtime.h>
#include <math.h>
#include <stdint.h>

#define BB 2
#define NN 1024
#define DD 512
#define HH 8
#define DHH 64
#define HD 512
#define FFD 2048
#define DEPTH 4

// ---------------- device scratch (no allocation allowed) ----------------
__device__ float g_x  [BB*NN*DD];
__device__ float g_xn [BB*NN*DD];
__device__ float g_qkv[BB*NN*3*HD];
__device__ float g_ws [BB*NN*HD];
__device__ float g_AC [(size_t)BB*HH*NN*NN];
__device__ float g_BD [(size_t)BB*HH*NN*NN];
__device__ float g_attn[(size_t)BB*HH*NN*NN];
__device__ float g_av [BB*NN*HD];
__device__ float g_h1 [BB*NN*FFD];
// transposed weights: [N,K] K-major for B operand
__device__ float g_wqkvT[DEPTH * 3*HD * DD];
__device__ float g_wktT [DEPTH * HD * DD];
__device__ float g_wkcT [DEPTH * HD * DD];
__device__ float g_wkpT [DEPTH * HD * DD];
__device__ float g_woutT[DEPTH * DD * HD];
__device__ float g_wff1T[DEPTH * FFD * DD];
__device__ float g_wff2T[DEPTH * DD * FFD];

__device__ __forceinline__ uint32_t tf32r(float x) {
    uint32_t y; asm("cvt.rna.tf32.f32 %0, %1;" : "=r"(y) : "f"(x)); return y;
}
__device__ __forceinline__ void mma8(float* d, const uint32_t* a, const uint32_t* b) {
    asm volatile("mma.sync.aligned.m16n8k8.row.col.f32.tf32.tf32.f32 "
        "{%0,%1,%2,%3}, {%4,%5,%6,%7}, {%8,%9}, {%0,%1,%2,%3};"
        : "+f"(d[0]), "+f"(d[1]), "+f"(d[2]), "+f"(d[3])
        : "r"(a[0]), "r"(a[1]), "r"(a[2]), "r"(a[3]), "r"(b[0]), "r"(b[1]));
}

// ---------------- simple copies ----------------
__global__ void copy_in_kernel(const float* __restrict__ src) {
    int i = blockIdx.x * 256 + threadIdx.x;
    g_x[i] = src[i];
}
__global__ void copy_out_kernel(float* __restrict__ dst) {
    int i = blockIdx.x * 256 + threadIdx.x;
    dst[i] = g_x[i];
}

// ---------------- weight transpose: src [R,C] (per layer) -> dst [C,R] ----------------
__global__ void transpose_batch(const float* __restrict__ src, float* __restrict__ dst,
                                int R, int C) {
    __shared__ float t[32][33];
    size_t off = (size_t)blockIdx.z * R * C;
    int c0 = blockIdx.x * 32, r0 = blockIdx.y * 32;
    int x = threadIdx.x, y = threadIdx.y;
#pragma unroll
    for (int i = 0; i < 32; i += 8)
        t[y + i][x] = src[off + (size_t)(r0 + y + i) * C + c0 + x];
    __syncthreads();
#pragma unroll
    for (int i = 0; i < 32; i += 8)
        dst[off + (size_t)(c0 + y + i) * R + r0 + x] = t[x][y + i];
}

// ---------------- layernorm ----------------
__global__ void ln_kernel(const float* __restrict__ x, const float* __restrict__ g,
                          const float* __restrict__ bta, float* __restrict__ y) {
    __shared__ float red[128];
    int row = blockIdx.x;
    int tid = threadIdx.x;
    const float4* xr = (const float4*)(x + (size_t)row * DD);
    float4 v = xr[tid];
    red[tid] = v.x + v.y + v.z + v.w;
    __syncthreads();
    for (int o = 64; o > 0; o >>= 1) { if (tid < o) red[tid] += red[tid + o]; __syncthreads(); }
    float mean = red[0] * (1.0f / DD);
    __syncthreads();
    float dx = v.x - mean, dy = v.y - mean, dz = v.z - mean, dw = v.w - mean;
    red[tid] = dx*dx + dy*dy + dz*dz + dw*dw;
    __syncthreads();
    for (int o = 64; o > 0; o >>= 1) { if (tid < o) red[tid] += red[tid + o]; __syncthreads(); }
    float rstd = rsqrtf(red[0] * (1.0f / DD) + 1e-5f);
    float4 gv = ((const float4*)g)[tid];
    float4 bv = ((const float4*)bta)[tid];
    float4 o4;
    o4.x = dx * rstd * gv.x + bv.x;
    o4.y = dy * rstd * gv.y + bv.y;
    o4.z = dz * rstd * gv.z + bv.z;
    o4.w = dw * rstd * gv.w + bv.w;
    ((float4*)(y + (size_t)row * DD))[tid] = o4;
}

__device__ __forceinline__ float gelu_exact(float v) {
    return 0.5f * v * (1.0f + erff(v * 0.70710678118654752f));
}

// ---------------- mma.sync tf32 GEMM: C[M,Nc] = A[M,K] @ Bt[Nc,K]^T ----------------
// CTA tile 128x64, BK=32, 8 warps (4 m x 2 n), warp tile 32x32 (2x4 of m16n8k8).
// smem: As[k][m] stride 136, Bs[k][n] stride 72 (pad 8 -> conflict-free frag loads).
#define AS_STRIDE 136
#define BS_STRIDE 72
#define A_BUF_W  (32 * AS_STRIDE)   // 4352 words
#define B_BUF_W  (32 * BS_STRIDE)   // 2304 words
#define MG_SMEM  ((2 * A_BUF_W + 2 * B_BUF_W) * 4)  // 53248 bytes

template<bool ACCUM, bool BIAS, bool RES, bool GELU_>
__global__ void __launch_bounds__(256, 2)
mgemm(const float* __restrict__ A, const float* __restrict__ Bt, float* __restrict__ C,
      int Nc, int K, const float* __restrict__ bias, const float* __restrict__ res) {
    extern __shared__ float sm[];
    float* sA[2] = { sm, sm + A_BUF_W };
    float* sB[2] = { sm + 2 * A_BUF_W, sm + 2 * A_BUF_W + B_BUF_W };

    const int tid = threadIdx.x;
    const int wid = tid >> 5, lid = tid & 31;
    const int row0 = blockIdx.y * 128;
    const int col0 = blockIdx.x * 64;

    // loader mapping
    const int arow = tid >> 1;            // 0..127
    const int akb  = (tid & 1) * 16;      // k base (16 floats)
    const int brow = tid >> 2;            // 0..63 (n)
    const int bkb  = (tid & 3) * 8;       // k base (8 floats)
    const float* gA = A  + (size_t)(row0 + arow) * K + akb;
    const float* gB = Bt + (size_t)(col0 + brow) * K + bkb;

    float acc[2][4][4];
#pragma unroll
    for (int mt = 0; mt < 2; mt++)
#pragma unroll
        for (int nt = 0; nt < 4; nt++)
#pragma unroll
            for (int r = 0; r < 4; r++) acc[mt][nt][r] = 0.f;

    float ar[16], br[8];
    const int nch = K >> 5;

    // prologue: chunk 0
#pragma unroll
    for (int i = 0; i < 4; i++) {
        float4 v = *(const float4*)(gA + i * 4);
        ar[4*i] = v.x; ar[4*i+1] = v.y; ar[4*i+2] = v.z; ar[4*i+3] = v.w;
    }
#pragma unroll
    for (int i = 0; i < 2; i++) {
        float4 v = *(const float4*)(gB + i * 4);
        br[4*i] = v.x; br[4*i+1] = v.y; br[4*i+2] = v.z; br[4*i+3] = v.w;
    }
#pragma unroll
    for (int i = 0; i < 16; i++)
        sA[0][(akb + i) * AS_STRIDE + arow] = __uint_as_float(tf32r(ar[i]));
#pragma unroll
    for (int i = 0; i < 8; i++)
        sB[0][(bkb + i) * BS_STRIDE + brow] = __uint_as_float(tf32r(br[i]));
    __syncthreads();

    const int wm = (wid & 3) * 32;
    const int wn = (wid >> 2) * 32;
    const int g  = lid >> 2;
    const int tg = lid & 3;

    int p = 0;
    for (int c = 0; c < nch; c++) {
        if (c + 1 < nch) {
            const float* pa = gA + (size_t)(c + 1) * 32;
            const float* pb = gB + (size_t)(c + 1) * 32;
#pragma unroll
            for (int i = 0; i < 4; i++) {
                float4 v = *(const float4*)(pa + i * 4);
                ar[4*i] = v.x; ar[4*i+1] = v.y; ar[4*i+2] = v.z; ar[4*i+3] = v.w;
            }
#pragma unroll
            for (int i = 0; i < 2; i++) {
                float4 v = *(const float4*)(pb + i * 4);
                br[4*i] = v.x; br[4*i+1] = v.y; br[4*i+2] = v.z; br[4*i+3] = v.w;
            }
        }
        const float* cA = sA[p];
        const float* cB = sB[p];
#pragma unroll
        for (int s = 0; s < 4; s++) {
            const int k0 = s * 8;
            uint32_t afr[2][4];
#pragma unroll
            for (int mt = 0; mt < 2; mt++) {
                int row = wm + mt * 16 + g;
                afr[mt][0] = __float_as_uint(cA[(k0 + tg)     * AS_STRIDE + row]);
                afr[mt][1] = __float_as_uint(cA[(k0 + tg)     * AS_STRIDE + row + 8]);
                afr[mt][2] = __float_as_uint(cA[(k0 + tg + 4) * AS_STRIDE + row]);
                afr[mt][3] = __float_as_uint(cA[(k0 + tg + 4) * AS_STRIDE + row + 8]);
            }
            uint32_t bfr[4][2];
#pragma unroll
            for (int nt = 0; nt < 4; nt++) {
                int cn = wn + nt * 8 + g;
                bfr[nt][0] = __float_as_uint(cB[(k0 + tg)     * BS_STRIDE + cn]);
                bfr[nt][1] = __float_as_uint(cB[(k0 + tg + 4) * BS_STRIDE + cn]);
            }
#pragma unroll
            for (int mt = 0; mt < 2; mt++)
#pragma unroll
                for (int nt = 0; nt < 4; nt++)
                    mma8(acc[mt][nt], afr[mt], bfr[nt]);
        }
        if (c + 1 < nch) {
            float* dA = sA[1 - p];
            float* dB = sB[1 - p];
#pragma unroll
            for (int i = 0; i < 16; i++)
                dA[(akb + i) * AS_STRIDE + arow] = __uint_as_float(tf32r(ar[i]));
#pragma unroll
            for (int i = 0; i < 8; i++)
                dB[(bkb + i) * BS_STRIDE + brow] = __uint_as_float(tf32r(br[i]));
        }
        __syncthreads();
        p ^= 1;
    }

    // epilogue
#pragma unroll
    for (int mt = 0; mt < 2; mt++) {
#pragma unroll
        for (int rh = 0; rh < 2; rh++) {
            int row = row0 + wm + mt * 16 + g + rh * 8;
#pragma unroll
            for (int nt = 0; nt < 4; nt++) {
                int col = col0 + wn + nt * 8 + tg * 2;
                size_t idx = (size_t)row * Nc + col;
                float v0 = acc[mt][nt][rh * 2 + 0];
                float v1 = acc[mt][nt][rh * 2 + 1];
                if (ACCUM) { float2 o = *(const float2*)(C + idx); v0 += o.x; v1 += o.y; }
                if (BIAS)  { float2 bv = *(const float2*)(bias + col); v0 += bv.x; v1 += bv.y; }
                if (RES)   { float2 rv = *(const float2*)(res + idx); v0 += rv.x; v1 += rv.y; }
                if (GELU_) { v0 = gelu_exact(v0); v1 = gelu_exact(v1); }
                float2 o2 = make_float2(v0, v1);
                *(float2*)(C + idx) = o2;
            }
        }
    }
}

// ---------------- batched scores: AC = q.k^T, BD = q.ws^T  (per b,h; K=64) ----------------
__global__ void scores_kernel(const float* __restrict__ qkv, const float* __restrict__ ws,
                              const float* __restrict__ bias_pf,
                              float* __restrict__ AC, float* __restrict__ BD) {
    __shared__ float Qs[DHH][64];
    __shared__ float Ks[DHH][64];
    __shared__ float Ws[DHH][64];
    const int bh = blockIdx.z;
    const int b = bh >> 3, h = bh & 7;
    const int i0 = blockIdx.y << 6, j0 = blockIdx.x << 6;
    const int tid = threadIdx.x;
    const int tx = tid & 15, ty = tid >> 4;

    const int lrow = tid >> 2;
    const int ld0  = (tid & 3) << 4;
    const float* qbase = qkv + (size_t)(b * NN + i0 + lrow) * (3 * HD) + h * DHH;
    const float* kbase = qkv + (size_t)(b * NN + j0 + lrow) * (3 * HD) + HD + h * DHH;
    const float* wbase = ws  + (size_t)(b * NN + j0 + lrow) * HD + h * DHH;
    const float* pfb   = bias_pf + h * DHH;
#pragma unroll
    for (int t = 0; t < 4; t++) {
        int d = ld0 + t * 4;
        float4 qv = *(const float4*)(qbase + d);
        float4 pf = *(const float4*)(pfb + d);
        Qs[d + 0][lrow] = qv.x + pf.x; Qs[d + 1][lrow] = qv.y + pf.y;
        Qs[d + 2][lrow] = qv.z + pf.z; Qs[d + 3][lrow] = qv.w + pf.w;
        float4 kv = *(const float4*)(kbase + d);
        Ks[d + 0][lrow] = kv.x; Ks[d + 1][lrow] = kv.y;
        Ks[d + 2][lrow] = kv.z; Ks[d + 3][lrow] = kv.w;
        float4 wv = *(const float4*)(wbase + d);
        Ws[d + 0][lrow] = wv.x; Ws[d + 1][lrow] = wv.y;
        Ws[d + 2][lrow] = wv.z; Ws[d + 3][lrow] = wv.w;
    }
    __syncthreads();

    float ac[4][4], bd[4][4];
#pragma unroll
    for (int r = 0; r < 4; r++)
#pragma unroll
        for (int c = 0; c < 4; c++) { ac[r][c] = 0.f; bd[r][c] = 0.f; }

#pragma unroll 8
    for (int d = 0; d < DHH; d++) {
        float qa[4], kb[4], wb[4];
#pragma unroll
        for (int r = 0; r < 4; r++) qa[r] = Qs[d][(ty << 2) + r];
#pragma unroll
        for (int c = 0; c < 4; c++) { kb[c] = Ks[d][(tx << 2) + c]; wb[c] = Ws[d][(tx << 2) + c]; }
#pragma unroll
        for (int r = 0; r < 4; r++)
#pragma unroll
            for (int c = 0; c < 4; c++) {
                ac[r][c] = fmaf(qa[r], kb[c], ac[r][c]);
                bd[r][c] = fmaf(qa[r], wb[c], bd[r][c]);
            }
    }
    const size_t base = ((size_t)bh << 20);
#pragma unroll
    for (int r = 0; r < 4; r++) {
        int i = i0 + (ty << 2) + r;
        size_t rb = base + ((size_t)i << 10) + j0 + (tx << 2);
        float4 a4 = make_float4(ac[r][0], ac[r][1], ac[r][2], ac[r][3]);
        float4 b4 = make_float4(bd[r][0], bd[r][1], bd[r][2], bd[r][3]);
        *(float4*)(AC + rb) = a4;
        *(float4*)(BD + rb) = b4;
    }
}

// ---------------- dots + rel_shift + softmax over heads ----------------
__global__ void softmax_kernel(const float* __restrict__ AC, const float* __restrict__ BD,
                               float* __restrict__ attn) {
    int idx = blockIdx.x * 256 + threadIdx.x;
    int b = idx >> 20;
    int ij = idx & ((1 << 20) - 1);
    int i = ij >> 10, j = ij & 1023;
    int m  = (i + 1) * NN + j;
    int i2 = m / (NN + 1);
    int k  = m - i2 * (NN + 1);
    size_t pb = ((size_t)(b * HH)) << 20;
    size_t shifted = ((size_t)i2 << 10) + (k - 1);
    float vals[8];
#pragma unroll
    for (int h = 0; h < 8; h++) {
        float ac = AC[pb + ((size_t)h << 20) + ij];
        float bd = (k != 0) ? BD[pb + ((size_t)h << 20) + shifted] : 0.f;
        vals[h] = (ac + bd * (1.0f / 3.0f)) * 0.125f;
    }
    float mx = vals[0];
#pragma unroll
    for (int h = 1; h < 8; h++) mx = fmaxf(mx, vals[h]);
    float s = 0.f;
#pragma unroll
    for (int h = 0; h < 8; h++) { vals[h] = expf(vals[h] - mx); s += vals[h]; }
    float inv = 1.0f / s;
#pragma unroll
    for (int h = 0; h < 8; h++) attn[pb + ((size_t)h << 20) + ij] = vals[h] * inv;
}

// ---------------- attn @ v ----------------
__global__ void attnv_kernel(const float* __restrict__ attn, const float* __restrict__ qkv,
                             float* __restrict__ av) {
    __shared__ float As[64][64];
    __shared__ float Vs[64][64];
    const int bh = blockIdx.y;
    const int b = bh >> 3, h = bh & 7;
    const int i0 = blockIdx.x << 6;
    const int tid = threadIdx.x;
    const int tx = tid & 15, ty = tid >> 4;
    const int lrow = tid >> 2;
    const int ld0  = (tid & 3) << 4;

    float acc[4][4];
#pragma unroll
    for (int r = 0; r < 4; r++)
#pragma unroll
        for (int c = 0; c < 4; c++) acc[r][c] = 0.f;

    for (int j0 = 0; j0 < NN; j0 += 64) {
        const float* arow = attn + (((size_t)bh) << 20) + ((size_t)(i0 + lrow) << 10) + j0;
        const float* vrow = qkv + (size_t)(b * NN + j0 + lrow) * (3 * HD) + 2 * HD + h * DHH;
#pragma unroll
        for (int t = 0; t < 4; t++) {
            int o = ld0 + t * 4;
            float4 a4 = *(const float4*)(arow + o);
            As[o + 0][lrow] = a4.x; As[o + 1][lrow] = a4.y;
            As[o + 2][lrow] = a4.z; As[o + 3][lrow] = a4.w;
            float4 v4 = *(const float4*)(vrow + o);
            *(float4*)&Vs[lrow][o] = v4;
        }
        __syncthreads();
#pragma unroll 8
        for (int jj = 0; jj < 64; jj++) {
            float a[4], v[4];
#pragma unroll
            for (int r = 0; r < 4; r++) a[r] = As[jj][(ty << 2) + r];
#pragma unroll
            for (int c = 0; c < 4; c++) v[c] = Vs[jj][(tx << 2) + c];
#pragma unroll
            for (int r = 0; r < 4; r++)
#pragma unroll
                for (int c = 0; c < 4; c++) acc[r][c] = fmaf(a[r], v[c], acc[r][c]);
        }
        __syncthreads();
    }
#pragma unroll
    for (int r = 0; r < 4; r++) {
        int i = i0 + (ty << 2) + r;
        float4 o4 = make_float4(acc[r][0], acc[r][1], acc[r][2], acc[r][3]);
        *(float4*)(av + (size_t)(b * NN + i) * HD + h * DHH + (tx << 2)) = o4;
    }
}

// ---------------- host orchestration ----------------
extern "C" void kernel_launch(void* const* d_in, const int* in_sizes, int n_in,
                              void* d_out, int out_size) {
    (void)in_sizes; (void)n_in; (void)out_size;
    const float* in_x   = (const float*)d_in[0];
    const float* r_t    = (const float*)d_in[1];
    const float* r_c    = (const float*)d_in[2];
    const float* r_p    = (const float*)d_in[3];
    const float* bias_pf= (const float*)d_in[4];
    const float* ln1_g  = (const float*)d_in[5];
    const float* ln1_b  = (const float*)d_in[6];
    const float* w_qkv  = (const float*)d_in[7];
    const float* w_out  = (const float*)d_in[8];
    const float* b_out  = (const float*)d_in[9];
    const float* w_kt   = (const float*)d_in[10];
    const float* w_kc   = (const float*)d_in[11];
    const float* w_kp   = (const float*)d_in[12];
    const float* ln2_g  = (const float*)d_in[13];
    const float* ln2_b  = (const float*)d_in[14];
    const float* w_ff1  = (const float*)d_in[15];
    const float* b_ff1  = (const float*)d_in[16];
    const float* w_ff2  = (const float*)d_in[17];
    const float* b_ff2  = (const float*)d_in[18];

    float* out_x    = (float*)d_out;
    float* out_attn = out_x + (size_t)BB * NN * DD;

    float *p_x, *p_xn, *p_qkv, *p_ws, *p_AC, *p_BD, *p_attn, *p_av, *p_h1;
    float *p_wqkvT, *p_wktT, *p_wkcT, *p_wkpT, *p_woutT, *p_wff1T, *p_wff2T;
    cudaGetSymbolAddress((void**)&p_x,   g_x);
    cudaGetSymbolAddress((void**)&p_xn,  g_xn);
    cudaGetSymbolAddress((void**)&p_qkv, g_qkv);
    cudaGetSymbolAddress((void**)&p_ws,  g_ws);
    cudaGetSymbolAddress((void**)&p_AC,  g_AC);
    cudaGetSymbolAddress((void**)&p_BD,  g_BD);
    cudaGetSymbolAddress((void**)&p_attn,g_attn);
    cudaGetSymbolAddress((void**)&p_av,  g_av);
    cudaGetSymbolAddress((void**)&p_h1,  g_h1);
    cudaGetSymbolAddress((void**)&p_wqkvT, g_wqkvT);
    cudaGetSymbolAddress((void**)&p_wktT,  g_wktT);
    cudaGetSymbolAddress((void**)&p_wkcT,  g_wkcT);
    cudaGetSymbolAddress((void**)&p_wkpT,  g_wkpT);
    cudaGetSymbolAddress((void**)&p_woutT, g_woutT);
    cudaGetSymbolAddress((void**)&p_wff1T, g_wff1T);
    cudaGetSymbolAddress((void**)&p_wff2T, g_wff2T);

    cudaFuncSetAttribute(mgemm<false,false,false,false>, cudaFuncAttributeMaxDynamicSharedMemorySize, MG_SMEM);
    cudaFuncSetAttribute(mgemm<true,false,false,false>,  cudaFuncAttributeMaxDynamicSharedMemorySize, MG_SMEM);
    cudaFuncSetAttribute(mgemm<false,true,true,false>,   cudaFuncAttributeMaxDynamicSharedMemorySize, MG_SMEM);
    cudaFuncSetAttribute(mgemm<false,true,false,true>,   cudaFuncAttributeMaxDynamicSharedMemorySize, MG_SMEM);

    const int M = BB * NN;   // 2048
    dim3 t32(32, 8);

    // one-time weight transposes
    transpose_batch<<<dim3(3*HD/32, DD/32, DEPTH), t32>>>(w_qkv, p_wqkvT, DD, 3*HD);
    transpose_batch<<<dim3(HD/32, DD/32, DEPTH),  t32>>>(w_kt,  p_wktT,  DD, HD);
    transpose_batch<<<dim3(HD/32, DD/32, DEPTH),  t32>>>(w_kc,  p_wkcT,  DD, HD);
    transpose_batch<<<dim3(HD/32, DD/32, DEPTH),  t32>>>(w_kp,  p_wkpT,  DD, HD);
    transpose_batch<<<dim3(DD/32, HD/32, DEPTH),  t32>>>(w_out, p_woutT, HD, DD);
    transpose_batch<<<dim3(FFD/32, DD/32, DEPTH), t32>>>(w_ff1, p_wff1T, DD, FFD);
    transpose_batch<<<dim3(DD/32, FFD/32, DEPTH), t32>>>(w_ff2, p_wff2T, FFD, DD);

    copy_in_kernel<<<(BB * NN * DD) / 256, 256>>>(in_x);

    for (int l = 0; l < DEPTH; l++) {
        ln_kernel<<<M, 128>>>(p_x, ln1_g + l * DD, ln1_b + l * DD, p_xn);
        // qkv = xn @ w_qkv[l]
        mgemm<false,false,false,false><<<dim3(24, 16), 256, MG_SMEM>>>(
            p_xn, p_wqkvT + (size_t)l * 3*HD * DD, p_qkv, 3 * HD, DD, nullptr, nullptr);
        // ws = r_t@w_kt + r_c@w_kc + r_p@w_kp
        mgemm<false,false,false,false><<<dim3(8, 16), 256, MG_SMEM>>>(
            r_t, p_wktT + (size_t)l * HD * DD, p_ws, HD, DD, nullptr, nullptr);
        mgemm<true,false,false,false><<<dim3(8, 16), 256, MG_SMEM>>>(
            r_c, p_wkcT + (size_t)l * HD * DD, p_ws, HD, DD, nullptr, nullptr);
        mgemm<true,false,false,false><<<dim3(8, 16), 256, MG_SMEM>>>(
            r_p, p_wkpT + (size_t)l * HD * DD, p_ws, HD, DD, nullptr, nullptr);
        // AC / BD batched scores
        scores_kernel<<<dim3(16, 16, BB * HH), 256>>>(p_qkv, p_ws, bias_pf, p_AC, p_BD);
        // dots + rel_shift gather + softmax over heads
        float* attn_dst = (l == DEPTH - 1) ? out_attn : p_attn;
        softmax_kernel<<<(BB * NN * NN) / 256, 256>>>(p_AC, p_BD, attn_dst);
        // attn @ v
        attnv_kernel<<<dim3(16, BB * HH), 256>>>(attn_dst, p_qkv, p_av);
        // out projection + bias + residual
        mgemm<false,true,true,false><<<dim3(8, 16), 256, MG_SMEM>>>(
            p_av, p_woutT + (size_t)l * DD * HD, p_x, DD, HD, b_out + l * DD, p_x);
        ln_kernel<<<M, 128>>>(p_x, ln2_g + l * DD, ln2_b + l * DD, p_xn);
        // FF1 + bias + exact GELU
        mgemm<false,true,false,true><<<dim3(32, 16), 256, MG_SMEM>>>(
            p_xn, p_wff1T + (size_t)l * FFD * DD, p_h1, FFD, DD, b_ff1 + l * FFD, nullptr);
        // FF2 + bias + residual
        mgemm<false,true,true,false><<<dim3(8, 16), 256, MG_SMEM>>>(
            p_h1, p_wff2T + (size_t)l * DD * FFD, p_x, DD, FFD, b_ff2 + l * DD, p_x);
    }

    copy_out_kernel<<<(BB * NN * DD) / 256, 256>>>(out_x);
}

// round 4
// speedup vs baseline: 2.5223x; 1.1798x over previous
#include <cuda_runtime.h>
#include <math.h>
#include <stdint.h>

#define BB 2
#define NN 1024
#define DD 512
#define HH 8
#define DHH 64
#define HD 512
#define FFD 2048
#define DEPTH 4

// ---------------- device scratch ----------------
__device__ float g_x  [BB*NN*DD];
__device__ float g_xn [BB*NN*DD];
__device__ float g_qkv[BB*NN*3*HD];
__device__ float g_ws [BB*NN*HD];
__device__ float g_AC [(size_t)BB*HH*NN*NN];
__device__ float g_BD [(size_t)BB*HH*NN*NN];
__device__ float g_attn[(size_t)BB*HH*NN*NN];
__device__ float g_av [BB*NN*HD];
__device__ float g_h1 [BB*NN*FFD];
__device__ float g_wqkvT[DEPTH * 3*HD * DD];
__device__ float g_wktT [DEPTH * HD * DD];
__device__ float g_wkcT [DEPTH * HD * DD];
__device__ float g_wkpT [DEPTH * HD * DD];
__device__ float g_woutT[DEPTH * DD * HD];
__device__ float g_wff1T[DEPTH * FFD * DD];
__device__ float g_wff2T[DEPTH * DD * FFD];

__device__ __forceinline__ uint32_t tf32r(float x) {
    uint32_t y; asm("cvt.rna.tf32.f32 %0, %1;" : "=r"(y) : "f"(x)); return y;
}
__device__ __forceinline__ float tf32f(float x) {
    return __uint_as_float(tf32r(x));
}
__device__ __forceinline__ void mma8(float* d, const uint32_t* a, const uint32_t* b) {
    asm volatile("mma.sync.aligned.m16n8k8.row.col.f32.tf32.tf32.f32 "
        "{%0,%1,%2,%3}, {%4,%5,%6,%7}, {%8,%9}, {%0,%1,%2,%3};"
        : "+f"(d[0]), "+f"(d[1]), "+f"(d[2]), "+f"(d[3])
        : "r"(a[0]), "r"(a[1]), "r"(a[2]), "r"(a[3]), "r"(b[0]), "r"(b[1]));
}

// ---------------- simple copies ----------------
__global__ void copy_in_kernel(const float* __restrict__ src) {
    int i = blockIdx.x * 256 + threadIdx.x;
    g_x[i] = src[i];
}
__global__ void copy_out_kernel(float* __restrict__ dst) {
    int i = blockIdx.x * 256 + threadIdx.x;
    dst[i] = g_x[i];
}

// ---------------- weight transpose ----------------
__global__ void transpose_batch(const float* __restrict__ src, float* __restrict__ dst,
                                int R, int C) {
    __shared__ float t[32][33];
    size_t off = (size_t)blockIdx.z * R * C;
    int c0 = blockIdx.x * 32, r0 = blockIdx.y * 32;
    int x = threadIdx.x, y = threadIdx.y;
#pragma unroll
    for (int i = 0; i < 32; i += 8)
        t[y + i][x] = src[off + (size_t)(r0 + y + i) * C + c0 + x];
    __syncthreads();
#pragma unroll
    for (int i = 0; i < 32; i += 8)
        dst[off + (size_t)(c0 + y + i) * R + r0 + x] = t[x][y + i];
}

// ---------------- layernorm ----------------
__global__ void ln_kernel(const float* __restrict__ x, const float* __restrict__ g,
                          const float* __restrict__ bta, float* __restrict__ y) {
    __shared__ float red[128];
    int row = blockIdx.x;
    int tid = threadIdx.x;
    const float4* xr = (const float4*)(x + (size_t)row * DD);
    float4 v = xr[tid];
    red[tid] = v.x + v.y + v.z + v.w;
    __syncthreads();
    for (int o = 64; o > 0; o >>= 1) { if (tid < o) red[tid] += red[tid + o]; __syncthreads(); }
    float mean = red[0] * (1.0f / DD);
    __syncthreads();
    float dx = v.x - mean, dy = v.y - mean, dz = v.z - mean, dw = v.w - mean;
    red[tid] = dx*dx + dy*dy + dz*dz + dw*dw;
    __syncthreads();
    for (int o = 64; o > 0; o >>= 1) { if (tid < o) red[tid] += red[tid + o]; __syncthreads(); }
    float rstd = rsqrtf(red[0] * (1.0f / DD) + 1e-5f);
    float4 gv = ((const float4*)g)[tid];
    float4 bv = ((const float4*)bta)[tid];
    float4 o4;
    o4.x = dx * rstd * gv.x + bv.x;
    o4.y = dy * rstd * gv.y + bv.y;
    o4.z = dz * rstd * gv.z + bv.z;
    o4.w = dw * rstd * gv.w + bv.w;
    ((float4*)(y + (size_t)row * DD))[tid] = o4;
}

__device__ __forceinline__ float gelu_exact(float v) {
    return 0.5f * v * (1.0f + erff(v * 0.70710678118654752f));
}

// ---------------- mma.sync tf32 GEMM: C[M,Nc] = A[M,K] @ Bt[Nc,K]^T ----------------
#define AS_STRIDE 136
#define BS_STRIDE 72
#define A_BUF_W  (32 * AS_STRIDE)
#define B_BUF_W  (32 * BS_STRIDE)
#define MG_SMEM  ((2 * A_BUF_W + 2 * B_BUF_W) * 4)

template<bool ACCUM, bool BIAS, bool RES, bool GELU_>
__global__ void __launch_bounds__(256, 2)
mgemm(const float* __restrict__ A, const float* __restrict__ Bt, float* __restrict__ C,
      int Nc, int K, const float* __restrict__ bias, const float* __restrict__ res) {
    extern __shared__ float sm[];
    float* sA[2] = { sm, sm + A_BUF_W };
    float* sB[2] = { sm + 2 * A_BUF_W, sm + 2 * A_BUF_W + B_BUF_W };

    const int tid = threadIdx.x;
    const int wid = tid >> 5, lid = tid & 31;
    const int row0 = blockIdx.y * 128;
    const int col0 = blockIdx.x * 64;

    const int arow = tid >> 1;
    const int akb  = (tid & 1) * 16;
    const int brow = tid >> 2;
    const int bkb  = (tid & 3) * 8;
    const float* gA = A  + (size_t)(row0 + arow) * K + akb;
    const float* gB = Bt + (size_t)(col0 + brow) * K + bkb;

    float acc[2][4][4];
#pragma unroll
    for (int mt = 0; mt < 2; mt++)
#pragma unroll
        for (int nt = 0; nt < 4; nt++)
#pragma unroll
            for (int r = 0; r < 4; r++) acc[mt][nt][r] = 0.f;

    float ar[16], br[8];
    const int nch = K >> 5;

#pragma unroll
    for (int i = 0; i < 4; i++) {
        float4 v = *(const float4*)(gA + i * 4);
        ar[4*i] = v.x; ar[4*i+1] = v.y; ar[4*i+2] = v.z; ar[4*i+3] = v.w;
    }
#pragma unroll
    for (int i = 0; i < 2; i++) {
        float4 v = *(const float4*)(gB + i * 4);
        br[4*i] = v.x; br[4*i+1] = v.y; br[4*i+2] = v.z; br[4*i+3] = v.w;
    }
#pragma unroll
    for (int i = 0; i < 16; i++)
        sA[0][(akb + i) * AS_STRIDE + arow] = tf32f(ar[i]);
#pragma unroll
    for (int i = 0; i < 8; i++)
        sB[0][(bkb + i) * BS_STRIDE + brow] = tf32f(br[i]);
    __syncthreads();

    const int wm = (wid & 3) * 32;
    const int wn = (wid >> 2) * 32;
    const int g  = lid >> 2;
    const int tg = lid & 3;

    int p = 0;
    for (int c = 0; c < nch; c++) {
        if (c + 1 < nch) {
            const float* pa = gA + (size_t)(c + 1) * 32;
            const float* pb = gB + (size_t)(c + 1) * 32;
#pragma unroll
            for (int i = 0; i < 4; i++) {
                float4 v = *(const float4*)(pa + i * 4);
                ar[4*i] = v.x; ar[4*i+1] = v.y; ar[4*i+2] = v.z; ar[4*i+3] = v.w;
            }
#pragma unroll
            for (int i = 0; i < 2; i++) {
                float4 v = *(const float4*)(pb + i * 4);
                br[4*i] = v.x; br[4*i+1] = v.y; br[4*i+2] = v.z; br[4*i+3] = v.w;
            }
        }
        const float* cA = sA[p];
        const float* cB = sB[p];
#pragma unroll
        for (int s = 0; s < 4; s++) {
            const int k0 = s * 8;
            uint32_t afr[2][4];
#pragma unroll
            for (int mt = 0; mt < 2; mt++) {
                int row = wm + mt * 16 + g;
                afr[mt][0] = __float_as_uint(cA[(k0 + tg)     * AS_STRIDE + row]);
                afr[mt][1] = __float_as_uint(cA[(k0 + tg)     * AS_STRIDE + row + 8]);
                afr[mt][2] = __float_as_uint(cA[(k0 + tg + 4) * AS_STRIDE + row]);
                afr[mt][3] = __float_as_uint(cA[(k0 + tg + 4) * AS_STRIDE + row + 8]);
            }
            uint32_t bfr[4][2];
#pragma unroll
            for (int nt = 0; nt < 4; nt++) {
                int cn = wn + nt * 8 + g;
                bfr[nt][0] = __float_as_uint(cB[(k0 + tg)     * BS_STRIDE + cn]);
                bfr[nt][1] = __float_as_uint(cB[(k0 + tg + 4) * BS_STRIDE + cn]);
            }
#pragma unroll
            for (int mt = 0; mt < 2; mt++)
#pragma unroll
                for (int nt = 0; nt < 4; nt++)
                    mma8(acc[mt][nt], afr[mt], bfr[nt]);
        }
        if (c + 1 < nch) {
            float* dA = sA[1 - p];
            float* dB = sB[1 - p];
#pragma unroll
            for (int i = 0; i < 16; i++)
                dA[(akb + i) * AS_STRIDE + arow] = tf32f(ar[i]);
#pragma unroll
            for (int i = 0; i < 8; i++)
                dB[(bkb + i) * BS_STRIDE + brow] = tf32f(br[i]);
        }
        __syncthreads();
        p ^= 1;
    }

#pragma unroll
    for (int mt = 0; mt < 2; mt++) {
#pragma unroll
        for (int rh = 0; rh < 2; rh++) {
            int row = row0 + wm + mt * 16 + g + rh * 8;
#pragma unroll
            for (int nt = 0; nt < 4; nt++) {
                int col = col0 + wn + nt * 8 + tg * 2;
                size_t idx = (size_t)row * Nc + col;
                float v0 = acc[mt][nt][rh * 2 + 0];
                float v1 = acc[mt][nt][rh * 2 + 1];
                if (ACCUM) { float2 o = *(const float2*)(C + idx); v0 += o.x; v1 += o.y; }
                if (BIAS)  { float2 bv = *(const float2*)(bias + col); v0 += bv.x; v1 += bv.y; }
                if (RES)   { float2 rv = *(const float2*)(res + idx); v0 += rv.x; v1 += rv.y; }
                if (GELU_) { v0 = gelu_exact(v0); v1 = gelu_exact(v1); }
                float2 o2 = make_float2(v0, v1);
                *(float2*)(C + idx) = o2;
            }
        }
    }
}

// ---------------- scores via mma: AC = Q.K^T, BD = Q.Ws^T (per b,h; K=64) ----------------
// 64x64 output tile per CTA; warps 0-3 -> AC, warps 4-7 -> BD (shared staged Q).
#define SC_STRIDE 72
#define SC_SMEM (3 * 64 * SC_STRIDE * 4)   // 55296 bytes
__global__ void __launch_bounds__(256, 4)
scores_mma(const float* __restrict__ qkv, const float* __restrict__ ws,
           const float* __restrict__ bias_pf,
           float* __restrict__ AC, float* __restrict__ BD) {
    extern __shared__ float sm[];
    float* Qs = sm;                       // [d][i]
    float* Ks = sm + 64 * SC_STRIDE;      // [d][j]
    float* Ws = sm + 128 * SC_STRIDE;     // [d][j]
    const int bh = blockIdx.z;
    const int b = bh >> 3, h = bh & 7;
    const int i0 = blockIdx.y << 6, j0 = blockIdx.x << 6;
    const int tid = threadIdx.x;

    // stage Q(+pf), K, Ws as tf32 in [k][row] layout
    const int r  = tid >> 2;
    const int d0 = (tid & 3) << 4;
    const float* qb = qkv + (size_t)(b * NN + i0 + r) * (3 * HD) + h * DHH + d0;
    const float* kb = qkv + (size_t)(b * NN + j0 + r) * (3 * HD) + HD + h * DHH + d0;
    const float* wb = ws  + (size_t)(b * NN + j0 + r) * HD + h * DHH + d0;
    const float* pf = bias_pf + h * DHH + d0;
#pragma unroll
    for (int t = 0; t < 4; t++) {
        float4 q4 = *(const float4*)(qb + t * 4);
        float4 p4 = *(const float4*)(pf + t * 4);
        int d = d0 + t * 4;
        Qs[(d + 0) * SC_STRIDE + r] = tf32f(q4.x + p4.x);
        Qs[(d + 1) * SC_STRIDE + r] = tf32f(q4.y + p4.y);
        Qs[(d + 2) * SC_STRIDE + r] = tf32f(q4.z + p4.z);
        Qs[(d + 3) * SC_STRIDE + r] = tf32f(q4.w + p4.w);
        float4 k4 = *(const float4*)(kb + t * 4);
        Ks[(d + 0) * SC_STRIDE + r] = tf32f(k4.x);
        Ks[(d + 1) * SC_STRIDE + r] = tf32f(k4.y);
        Ks[(d + 2) * SC_STRIDE + r] = tf32f(k4.z);
        Ks[(d + 3) * SC_STRIDE + r] = tf32f(k4.w);
        float4 w4 = *(const float4*)(wb + t * 4);
        Ws[(d + 0) * SC_STRIDE + r] = tf32f(w4.x);
        Ws[(d + 1) * SC_STRIDE + r] = tf32f(w4.y);
        Ws[(d + 2) * SC_STRIDE + r] = tf32f(w4.z);
        Ws[(d + 3) * SC_STRIDE + r] = tf32f(w4.w);
    }
    __syncthreads();

    const int wid = tid >> 5, lid = tid & 31;
    const int grp = wid >> 2;                 // 0: AC, 1: BD
    const int w2  = wid & 3;
    const int wm  = (w2 & 1) * 32;
    const int wn  = (w2 >> 1) * 32;
    const float* Bm = grp ? Ws : Ks;
    const int g = lid >> 2, tg = lid & 3;

    float acc[2][4][4];
#pragma unroll
    for (int mt = 0; mt < 2; mt++)
#pragma unroll
        for (int nt = 0; nt < 4; nt++)
#pragma unroll
            for (int q = 0; q < 4; q++) acc[mt][nt][q] = 0.f;

#pragma unroll
    for (int s = 0; s < 8; s++) {
        const int k0 = s * 8;
        uint32_t afr[2][4];
#pragma unroll
        for (int mt = 0; mt < 2; mt++) {
            int row = wm + mt * 16 + g;
            afr[mt][0] = __float_as_uint(Qs[(k0 + tg)     * SC_STRIDE + row]);
            afr[mt][1] = __float_as_uint(Qs[(k0 + tg)     * SC_STRIDE + row + 8]);
            afr[mt][2] = __float_as_uint(Qs[(k0 + tg + 4) * SC_STRIDE + row]);
            afr[mt][3] = __float_as_uint(Qs[(k0 + tg + 4) * SC_STRIDE + row + 8]);
        }
        uint32_t bfr[4][2];
#pragma unroll
        for (int nt = 0; nt < 4; nt++) {
            int cn = wn + nt * 8 + g;
            bfr[nt][0] = __float_as_uint(Bm[(k0 + tg)     * SC_STRIDE + cn]);
            bfr[nt][1] = __float_as_uint(Bm[(k0 + tg + 4) * SC_STRIDE + cn]);
        }
#pragma unroll
        for (int mt = 0; mt < 2; mt++)
#pragma unroll
            for (int nt = 0; nt < 4; nt++)
                mma8(acc[mt][nt], afr[mt], bfr[nt]);
    }

    float* Out = grp ? BD : AC;
    const size_t base = ((size_t)bh << 20);
#pragma unroll
    for (int mt = 0; mt < 2; mt++) {
#pragma unroll
        for (int rh = 0; rh < 2; rh++) {
            int i = i0 + wm + mt * 16 + g + rh * 8;
#pragma unroll
            for (int nt = 0; nt < 4; nt++) {
                int j = j0 + wn + nt * 8 + tg * 2;
                float2 o2 = make_float2(acc[mt][nt][rh * 2 + 0], acc[mt][nt][rh * 2 + 1]);
                *(float2*)(Out + base + ((size_t)i << 10) + j) = o2;
            }
        }
    }
}

// ---------------- dots + rel_shift + softmax over heads ----------------
__global__ void softmax_kernel(const float* __restrict__ AC, const float* __restrict__ BD,
                               float* __restrict__ attn) {
    int idx = blockIdx.x * 256 + threadIdx.x;
    int b = idx >> 20;
    int ij = idx & ((1 << 20) - 1);
    int i = ij >> 10, j = ij & 1023;
    int m  = (i + 1) * NN + j;
    int i2 = m / (NN + 1);
    int k  = m - i2 * (NN + 1);
    size_t pb = ((size_t)(b * HH)) << 20;
    size_t shifted = ((size_t)i2 << 10) + (k - 1);
    float vals[8];
#pragma unroll
    for (int h = 0; h < 8; h++) {
        float ac = AC[pb + ((size_t)h << 20) + ij];
        float bd = (k != 0) ? BD[pb + ((size_t)h << 20) + shifted] : 0.f;
        vals[h] = (ac + bd * (1.0f / 3.0f)) * 0.125f;
    }
    float mx = vals[0];
#pragma unroll
    for (int h = 1; h < 8; h++) mx = fmaxf(mx, vals[h]);
    float s = 0.f;
#pragma unroll
    for (int h = 0; h < 8; h++) { vals[h] = expf(vals[h] - mx); s += vals[h]; }
    float inv = 1.0f / s;
#pragma unroll
    for (int h = 0; h < 8; h++) attn[pb + ((size_t)h << 20) + ij] = vals[h] * inv;
}

// ---------------- attn @ v via mma (per b,h; M=1024, N=64, K=1024) ----------------
__global__ void __launch_bounds__(256, 2)
attnv_mma(const float* __restrict__ attn, const float* __restrict__ qkv,
          float* __restrict__ av) {
    extern __shared__ float sm[];
    float* sA[2] = { sm, sm + A_BUF_W };
    float* sB[2] = { sm + 2 * A_BUF_W, sm + 2 * A_BUF_W + B_BUF_W };

    const int bh = blockIdx.y;
    const int b = bh >> 3, h = bh & 7;
    const int i0 = blockIdx.x << 7;
    const int tid = threadIdx.x;
    const int wid = tid >> 5, lid = tid & 31;

    const int arow = tid >> 1;
    const int akb  = (tid & 1) * 16;
    const int bj   = tid >> 3;           // 0..31 (k-row within chunk)
    const int bd0  = (tid & 7) * 8;      // d base
    const float* gA = attn + ((size_t)bh << 20) + ((size_t)(i0 + arow) << 10) + akb;
    const float* gBbase = qkv + 2 * HD + h * DHH + bd0;  // + (b*NN + j)*1536

    float acc[2][4][4];
#pragma unroll
    for (int mt = 0; mt < 2; mt++)
#pragma unroll
        for (int nt = 0; nt < 4; nt++)
#pragma unroll
            for (int q = 0; q < 4; q++) acc[mt][nt][q] = 0.f;

    float ar[16], br[8];
    const int nch = NN >> 5;  // 32

    {
        const float* gB = gBbase + (size_t)(b * NN + bj) * (3 * HD);
#pragma unroll
        for (int i = 0; i < 4; i++) {
            float4 v = *(const float4*)(gA + i * 4);
            ar[4*i] = v.x; ar[4*i+1] = v.y; ar[4*i+2] = v.z; ar[4*i+3] = v.w;
        }
#pragma unroll
        for (int i = 0; i < 2; i++) {
            float4 v = *(const float4*)(gB + i * 4);
            br[4*i] = v.x; br[4*i+1] = v.y; br[4*i+2] = v.z; br[4*i+3] = v.w;
        }
#pragma unroll
        for (int i = 0; i < 16; i++)
            sA[0][(akb + i) * AS_STRIDE + arow] = tf32f(ar[i]);
#pragma unroll
        for (int i = 0; i < 8; i++)
            sB[0][bj * BS_STRIDE + bd0 + i] = tf32f(br[i]);
    }
    __syncthreads();

    const int wm = (wid & 3) * 32;
    const int wn = (wid >> 2) * 32;
    const int g  = lid >> 2;
    const int tg = lid & 3;

    int p = 0;
    for (int c = 0; c < nch; c++) {
        if (c + 1 < nch) {
            const float* pa = gA + (size_t)(c + 1) * 32;
            const float* pb = gBbase + (size_t)(b * NN + (c + 1) * 32 + bj) * (3 * HD);
#pragma unroll
            for (int i = 0; i < 4; i++) {
                float4 v = *(const float4*)(pa + i * 4);
                ar[4*i] = v.x; ar[4*i+1] = v.y; ar[4*i+2] = v.z; ar[4*i+3] = v.w;
            }
#pragma unroll
            for (int i = 0; i < 2; i++) {
                float4 v = *(const float4*)(pb + i * 4);
                br[4*i] = v.x; br[4*i+1] = v.y; br[4*i+2] = v.z; br[4*i+3] = v.w;
            }
        }
        const float* cA = sA[p];
        const float* cB = sB[p];
#pragma unroll
        for (int s = 0; s < 4; s++) {
            const int k0 = s * 8;
            uint32_t afr[2][4];
#pragma unroll
            for (int mt = 0; mt < 2; mt++) {
                int row = wm + mt * 16 + g;
                afr[mt][0] = __float_as_uint(cA[(k0 + tg)     * AS_STRIDE + row]);
                afr[mt][1] = __float_as_uint(cA[(k0 + tg)     * AS_STRIDE + row + 8]);
                afr[mt][2] = __float_as_uint(cA[(k0 + tg + 4) * AS_STRIDE + row]);
                afr[mt][3] = __float_as_uint(cA[(k0 + tg + 4) * AS_STRIDE + row + 8]);
            }
            uint32_t bfr[4][2];
#pragma unroll
            for (int nt = 0; nt < 4; nt++) {
                int cn = wn + nt * 8 + g;
                bfr[nt][0] = __float_as_uint(cB[(k0 + tg)     * BS_STRIDE + cn]);
                bfr[nt][1] = __float_as_uint(cB[(k0 + tg + 4) * BS_STRIDE + cn]);
            }
#pragma unroll
            for (int mt = 0; mt < 2; mt++)
#pragma unroll
                for (int nt = 0; nt < 4; nt++)
                    mma8(acc[mt][nt], afr[mt], bfr[nt]);
        }
        if (c + 1 < nch) {
            float* dA = sA[1 - p];
            float* dB = sB[1 - p];
#pragma unroll
            for (int i = 0; i < 16; i++)
                dA[(akb + i) * AS_STRIDE + arow] = tf32f(ar[i]);
#pragma unroll
            for (int i = 0; i < 8; i++)
                dB[bj * BS_STRIDE + bd0 + i] = tf32f(br[i]);
        }
        __syncthreads();
        p ^= 1;
    }

#pragma unroll
    for (int mt = 0; mt < 2; mt++) {
#pragma unroll
        for (int rh = 0; rh < 2; rh++) {
            int row = i0 + wm + mt * 16 + g + rh * 8;
#pragma unroll
            for (int nt = 0; nt < 4; nt++) {
                int col = wn + nt * 8 + tg * 2;
                float2 o2 = make_float2(acc[mt][nt][rh * 2 + 0], acc[mt][nt][rh * 2 + 1]);
                *(float2*)(av + (size_t)(b * NN + row) * HD + h * DHH + col) = o2;
            }
        }
    }
}

// ---------------- host orchestration ----------------
extern "C" void kernel_launch(void* const* d_in, const int* in_sizes, int n_in,
                              void* d_out, int out_size) {
    (void)in_sizes; (void)n_in; (void)out_size;
    const float* in_x   = (const float*)d_in[0];
    const float* r_t    = (const float*)d_in[1];
    const float* r_c    = (const float*)d_in[2];
    const float* r_p    = (const float*)d_in[3];
    const float* bias_pf= (const float*)d_in[4];
    const float* ln1_g  = (const float*)d_in[5];
    const float* ln1_b  = (const float*)d_in[6];
    const float* w_qkv  = (const float*)d_in[7];
    const float* w_out  = (const float*)d_in[8];
    const float* b_out  = (const float*)d_in[9];
    const float* w_kt   = (const float*)d_in[10];
    const float* w_kc   = (const float*)d_in[11];
    const float* w_kp   = (const float*)d_in[12];
    const float* ln2_g  = (const float*)d_in[13];
    const float* ln2_b  = (const float*)d_in[14];
    const float* w_ff1  = (const float*)d_in[15];
    const float* b_ff1  = (const float*)d_in[16];
    const float* w_ff2  = (const float*)d_in[17];
    const float* b_ff2  = (const float*)d_in[18];

    float* out_x    = (float*)d_out;
    float* out_attn = out_x + (size_t)BB * NN * DD;

    float *p_x, *p_xn, *p_qkv, *p_ws, *p_AC, *p_BD, *p_attn, *p_av, *p_h1;
    float *p_wqkvT, *p_wktT, *p_wkcT, *p_wkpT, *p_woutT, *p_wff1T, *p_wff2T;
    cudaGetSymbolAddress((void**)&p_x,   g_x);
    cudaGetSymbolAddress((void**)&p_xn,  g_xn);
    cudaGetSymbolAddress((void**)&p_qkv, g_qkv);
    cudaGetSymbolAddress((void**)&p_ws,  g_ws);
    cudaGetSymbolAddress((void**)&p_AC,  g_AC);
    cudaGetSymbolAddress((void**)&p_BD,  g_BD);
    cudaGetSymbolAddress((void**)&p_attn,g_attn);
    cudaGetSymbolAddress((void**)&p_av,  g_av);
    cudaGetSymbolAddress((void**)&p_h1,  g_h1);
    cudaGetSymbolAddress((void**)&p_wqkvT, g_wqkvT);
    cudaGetSymbolAddress((void**)&p_wktT,  g_wktT);
    cudaGetSymbolAddress((void**)&p_wkcT,  g_wkcT);
    cudaGetSymbolAddress((void**)&p_wkpT,  g_wkpT);
    cudaGetSymbolAddress((void**)&p_woutT, g_woutT);
    cudaGetSymbolAddress((void**)&p_wff1T, g_wff1T);
    cudaGetSymbolAddress((void**)&p_wff2T, g_wff2T);

    cudaFuncSetAttribute(mgemm<false,false,false,false>, cudaFuncAttributeMaxDynamicSharedMemorySize, MG_SMEM);
    cudaFuncSetAttribute(mgemm<true,false,false,false>,  cudaFuncAttributeMaxDynamicSharedMemorySize, MG_SMEM);
    cudaFuncSetAttribute(mgemm<false,true,true,false>,   cudaFuncAttributeMaxDynamicSharedMemorySize, MG_SMEM);
    cudaFuncSetAttribute(mgemm<false,true,false,true>,   cudaFuncAttributeMaxDynamicSharedMemorySize, MG_SMEM);
    cudaFuncSetAttribute(scores_mma, cudaFuncAttributeMaxDynamicSharedMemorySize, SC_SMEM);
    cudaFuncSetAttribute(attnv_mma,  cudaFuncAttributeMaxDynamicSharedMemorySize, MG_SMEM);

    const int M = BB * NN;   // 2048
    dim3 t32(32, 8);

    transpose_batch<<<dim3(3*HD/32, DD/32, DEPTH), t32>>>(w_qkv, p_wqkvT, DD, 3*HD);
    transpose_batch<<<dim3(HD/32, DD/32, DEPTH),  t32>>>(w_kt,  p_wktT,  DD, HD);
    transpose_batch<<<dim3(HD/32, DD/32, DEPTH),  t32>>>(w_kc,  p_wkcT,  DD, HD);
    transpose_batch<<<dim3(HD/32, DD/32, DEPTH),  t32>>>(w_kp,  p_wkpT,  DD, HD);
    transpose_batch<<<dim3(DD/32, HD/32, DEPTH),  t32>>>(w_out, p_woutT, HD, DD);
    transpose_batch<<<dim3(FFD/32, DD/32, DEPTH), t32>>>(w_ff1, p_wff1T, DD, FFD);
    transpose_batch<<<dim3(DD/32, FFD/32, DEPTH), t32>>>(w_ff2, p_wff2T, FFD, DD);

    copy_in_kernel<<<(BB * NN * DD) / 256, 256>>>(in_x);

    for (int l = 0; l < DEPTH; l++) {
        ln_kernel<<<M, 128>>>(p_x, ln1_g + l * DD, ln1_b + l * DD, p_xn);
        mgemm<false,false,false,false><<<dim3(24, 16), 256, MG_SMEM>>>(
            p_xn, p_wqkvT + (size_t)l * 3*HD * DD, p_qkv, 3 * HD, DD, nullptr, nullptr);
        mgemm<false,false,false,false><<<dim3(8, 16), 256, MG_SMEM>>>(
            r_t, p_wktT + (size_t)l * HD * DD, p_ws, HD, DD, nullptr, nullptr);
        mgemm<true,false,false,false><<<dim3(8, 16), 256, MG_SMEM>>>(
            r_c, p_wkcT + (size_t)l * HD * DD, p_ws, HD, DD, nullptr, nullptr);
        mgemm<true,false,false,false><<<dim3(8, 16), 256, MG_SMEM>>>(
            r_p, p_wkpT + (size_t)l * HD * DD, p_ws, HD, DD, nullptr, nullptr);
        scores_mma<<<dim3(16, 16, BB * HH), 256, SC_SMEM>>>(p_qkv, p_ws, bias_pf, p_AC, p_BD);
        float* attn_dst = (l == DEPTH - 1) ? out_attn : p_attn;
        softmax_kernel<<<(BB * NN * NN) / 256, 256>>>(p_AC, p_BD, attn_dst);
        attnv_mma<<<dim3(8, BB * HH), 256, MG_SMEM>>>(attn_dst, p_qkv, p_av);
        mgemm<false,true,true,false><<<dim3(8, 16), 256, MG_SMEM>>>(
            p_av, p_woutT + (size_t)l * DD * HD, p_x, DD, HD, b_out + l * DD, p_x);
        ln_kernel<<<M, 128>>>(p_x, ln2_g + l * DD, ln2_b + l * DD, p_xn);
        mgemm<false,true,false,true><<<dim3(32, 16), 256, MG_SMEM>>>(
            p_xn, p_wff1T + (size_t)l * FFD * DD, p_h1, FFD, DD, b_ff1 + l * FFD, nullptr);
        mgemm<false,true,true,false><<<dim3(8, 16), 256, MG_SMEM>>>(
            p_h1, p_wff2T + (size_t)l * DD * FFD, p_x, DD, FFD, b_ff2 + l * DD, p_x);
    }

    copy_out_kernel<<<(BB * NN * DD) / 256, 256>>>(out_x);
}